// round 1
// baseline (speedup 1.0000x reference)
#include <cuda_runtime.h>
#include <cstdint>

#define MROWS 32768
#define NQ 3
#define NE 256
#define ED 32
#define CBPAD 33

// ---------------- scratch (__device__ globals: allocation-free) ----------------
__device__ float g_loss;
__device__ float g_h0[(size_t)MROWS * 512];
__device__ float g_h1[(size_t)MROWS * 256];
__device__ float g_h2[(size_t)MROWS * 128];
__device__ float g_lat[(size_t)MROWS * ED];
__device__ float g_xq [(size_t)MROWS * ED];
__device__ float g_g0[(size_t)MROWS * 128];
__device__ float g_g1[(size_t)MROWS * 256];
__device__ float g_g2[(size_t)MROWS * 512];

// ---------------- generic fp32 GEMM:  C = relu?(A(MxK) * W(NxK)^T + bias) ----------------
template<int BM, int BN, int BK, int TM, int TN, bool RELU>
__global__ void __launch_bounds__((BM/TM)*(BN/TN))
gemm_nt_kernel(const float* __restrict__ A, const float* __restrict__ W,
               const float* __restrict__ bias, float* __restrict__ C,
               int M, int N, int K)
{
    constexpr int THREADS = (BM/TM)*(BN/TN);
    __shared__ float As[BK][BM];
    __shared__ float Ws[BK][BN];

    const int bm = blockIdx.y * BM;
    const int bn = blockIdx.x * BN;
    const int tid = threadIdx.x;
    const int tn = (tid % (BN/TN)) * TN;
    const int tm = (tid / (BN/TN)) * TM;

    float acc[TM][TN];
    #pragma unroll
    for (int i = 0; i < TM; i++)
        #pragma unroll
        for (int j = 0; j < TN; j++)
            acc[i][j] = 0.f;

    for (int k0 = 0; k0 < K; k0 += BK) {
        constexpr int A_LOADS = (BM*BK) / (4*THREADS);
        #pragma unroll
        for (int i = 0; i < A_LOADS; i++) {
            int idx = (tid + i*THREADS) * 4;
            int r = idx / BK, c = idx % BK;
            float4 v = *(const float4*)(A + (size_t)(bm + r)*K + k0 + c);
            As[c+0][r] = v.x; As[c+1][r] = v.y; As[c+2][r] = v.z; As[c+3][r] = v.w;
        }
        constexpr int W_LOADS = (BN*BK) / (4*THREADS);
        #pragma unroll
        for (int i = 0; i < W_LOADS; i++) {
            int idx = (tid + i*THREADS) * 4;
            int r = idx / BK, c = idx % BK;
            float4 v = *(const float4*)(W + (size_t)(bn + r)*K + k0 + c);
            Ws[c+0][r] = v.x; Ws[c+1][r] = v.y; Ws[c+2][r] = v.z; Ws[c+3][r] = v.w;
        }
        __syncthreads();

        #pragma unroll
        for (int k = 0; k < BK; k++) {
            float ar[TM], wr[TN];
            #pragma unroll
            for (int i = 0; i < TM; i += 4) {
                float4 v = *(const float4*)(&As[k][tm + i]);
                ar[i+0] = v.x; ar[i+1] = v.y; ar[i+2] = v.z; ar[i+3] = v.w;
            }
            #pragma unroll
            for (int j = 0; j < TN; j += 4) {
                float4 v = *(const float4*)(&Ws[k][tn + j]);
                wr[j+0] = v.x; wr[j+1] = v.y; wr[j+2] = v.z; wr[j+3] = v.w;
            }
            #pragma unroll
            for (int i = 0; i < TM; i++)
                #pragma unroll
                for (int j = 0; j < TN; j++)
                    acc[i][j] = fmaf(ar[i], wr[j], acc[i][j]);
        }
        __syncthreads();
    }

    #pragma unroll
    for (int i = 0; i < TM; i++) {
        #pragma unroll
        for (int j = 0; j < TN; j++) {
            float v = acc[i][j] + bias[bn + tn + j];
            if (RELU) v = fmaxf(v, 0.f);
            C[(size_t)(bm + tm + i)*N + bn + tn + j] = v;
        }
    }
}

// ---------------- fused residual-VQ kernel ----------------
// 256 threads = 256 codebook entries; block handles rows_per_block rows.
__global__ void __launch_bounds__(NE)
vq_kernel(const float* __restrict__ latent,
          const float* __restrict__ cb0, const float* __restrict__ cb1,
          const float* __restrict__ cb2,
          float* __restrict__ xq,
          float* __restrict__ out_idx, float* __restrict__ out_oh,
          float* __restrict__ out_logits,
          int rows_per_block)
{
    extern __shared__ float sm[];
    float* cbs   = sm;                        // NQ*NE*CBPAD
    float* cnorm = cbs + NQ*NE*CBPAD;         // NQ*NE
    float* resid = cnorm + NQ*NE;             // ED
    float* xqrow = resid + ED;                // ED
    float* red_v = xqrow + ED;                // NE
    int*   red_i = (int*)(red_v + NE);        // NE (ints)
    float* s_rn  = (float*)(red_i + NE);      // 1

    const int t = threadIdx.x;

    // load codebooks into padded smem (conflict-free column access)
    const float* srcs[NQ] = {cb0, cb1, cb2};
    for (int q = 0; q < NQ; q++)
        for (int i = t; i < NE*ED; i += NE) {
            int r = i / ED, c = i % ED;
            cbs[(q*NE + r)*CBPAD + c] = srcs[q][i];
        }
    __syncthreads();
    // precompute ||c||^2
    for (int q = 0; q < NQ; q++) {
        const float* row = &cbs[(q*NE + t)*CBPAD];
        float s = 0.f;
        #pragma unroll
        for (int k = 0; k < ED; k++) s = fmaf(row[k], row[k], s);
        cnorm[q*NE + t] = s;
    }
    __syncthreads();

    float loss_acc = 0.f;
    const int row0 = blockIdx.x * rows_per_block;
    const int row1 = min(row0 + rows_per_block, MROWS);

    for (int r = row0; r < row1; r++) {
        if (t < ED) { resid[t] = latent[(size_t)r*ED + t]; xqrow[t] = 0.f; }
        __syncthreads();

        for (int q = 0; q < NQ; q++) {
            // ||residual||^2 (warp 0)
            if (t < 32) {
                float v = resid[t]; v = v*v;
                #pragma unroll
                for (int o = 16; o; o >>= 1) v += __shfl_xor_sync(0xffffffffu, v, o);
                if (t == 0) s_rn[0] = v;
            }
            __syncthreads();
            const float rnorm = s_rn[0];

            // distance to code t (reference formula: ||r||^2 + ||c||^2 - 2 r.c)
            const float* crow = &cbs[(q*NE + t)*CBPAD];
            float dot = 0.f;
            #pragma unroll
            for (int k = 0; k < ED; k++) dot = fmaf(resid[k], crow[k], dot);
            float d = rnorm + cnorm[q*NE + t] - 2.f*dot;
            out_logits[((size_t)r*NQ + q)*NE + t] = d;

            // block argmin, first-occurrence tie-break (matches jnp.argmin)
            red_v[t] = d; red_i[t] = t;
            __syncthreads();
            #pragma unroll
            for (int s = NE/2; s > 0; s >>= 1) {
                if (t < s) {
                    float v2 = red_v[t+s]; int i2 = red_i[t+s];
                    if (v2 < red_v[t] || (v2 == red_v[t] && i2 < red_i[t])) {
                        red_v[t] = v2; red_i[t] = i2;
                    }
                }
                __syncthreads();
            }
            const int best = red_i[0];

            out_oh[((size_t)r*NQ + q)*NE + t] = (t == best) ? 1.f : 0.f;
            if (t == 0) out_idx[(size_t)r*NQ + q] = (float)best;

            // loss + residual / x_q updates (replicate reference arithmetic)
            if (t < 32) {
                float c  = cbs[(q*NE + best)*CBPAD + t];
                float rv = resid[t];
                float diff = c - rv;          // x_q - residual
                float xres = rv + diff;       // x_q_st forward value
                float sq = diff*diff;
                #pragma unroll
                for (int o = 16; o; o >>= 1) sq += __shfl_xor_sync(0xffffffffu, sq, o);
                if (t == 0) loss_acc += sq;
                resid[t] = rv - xres;
                xqrow[t] += xres;
            }
            __syncthreads();
        }
        if (t < ED) xq[(size_t)r*ED + t] = xqrow[t];
        __syncthreads();
    }
    if (t == 0) atomicAdd(&g_loss, loss_acc);
}

__global__ void zero_loss_kernel() { g_loss = 0.f; }

__global__ void finalize_kernel(float* __restrict__ loss_out)
{
    // rq_loss = mean over q of 1.25 * mean((xq - r)^2)  = total_sq * 1.25/(3*B*32)
    loss_out[0] = g_loss * (1.25f / (3.0f * (float)MROWS * (float)ED));
}

// ---------------- launch ----------------
extern "C" void kernel_launch(void* const* d_in, const int* in_sizes, int n_in,
                              void* d_out, int out_size)
{
    const float* x   = (const float*)d_in[0];
    const float* ew[4] = {(const float*)d_in[1], (const float*)d_in[3],
                          (const float*)d_in[5], (const float*)d_in[7]};
    const float* eb[4] = {(const float*)d_in[2], (const float*)d_in[4],
                          (const float*)d_in[6], (const float*)d_in[8]};
    const float* dw[4] = {(const float*)d_in[9],  (const float*)d_in[11],
                          (const float*)d_in[13], (const float*)d_in[15]};
    const float* db[4] = {(const float*)d_in[10], (const float*)d_in[12],
                          (const float*)d_in[14], (const float*)d_in[16]};
    const float* cb0 = (const float*)d_in[17];
    const float* cb1 = (const float*)d_in[18];
    const float* cb2 = (const float*)d_in[19];
    float* out = (float*)d_out;

    float *h0, *h1, *h2, *lat, *xq, *g0, *g1, *g2;
    cudaGetSymbolAddress((void**)&h0,  g_h0);
    cudaGetSymbolAddress((void**)&h1,  g_h1);
    cudaGetSymbolAddress((void**)&h2,  g_h2);
    cudaGetSymbolAddress((void**)&lat, g_lat);
    cudaGetSymbolAddress((void**)&xq,  g_xq);
    cudaGetSymbolAddress((void**)&g0,  g_g0);
    cudaGetSymbolAddress((void**)&g1,  g_g1);
    cudaGetSymbolAddress((void**)&g2,  g_g2);

    // output layout (all float32, tuple order, flattened)
    const size_t OFF_OUT  = 0;
    const size_t OFF_LOSS = (size_t)MROWS * 1024;
    const size_t OFF_IDX  = OFF_LOSS + 1;
    const size_t OFF_OH   = OFF_IDX + (size_t)MROWS * NQ;
    const size_t OFF_LG   = OFF_OH  + (size_t)MROWS * NQ * NE;

    const dim3 gy(1, MROWS/128);

    // encoder (fp32 throughout: argmin margins require full precision)
    gemm_nt_kernel<128,128,16,8,8,true ><<<dim3(512/128,  MROWS/128), 256>>>(x,  ew[0], eb[0], h0,  MROWS, 512, 1024);
    gemm_nt_kernel<128,128,16,8,8,true ><<<dim3(256/128,  MROWS/128), 256>>>(h0, ew[1], eb[1], h1,  MROWS, 256, 512);
    gemm_nt_kernel<128,128,16,8,8,true ><<<dim3(1,        MROWS/128), 256>>>(h1, ew[2], eb[2], h2,  MROWS, 128, 256);
    gemm_nt_kernel<128, 32,16,8,4,false><<<dim3(1,        MROWS/128), 128>>>(h2, ew[3], eb[3], lat, MROWS,  32, 128);

    // residual VQ
    zero_loss_kernel<<<1,1>>>();
    const size_t vq_smem = (size_t)(NQ*NE*CBPAD + NQ*NE + 2*ED + NE)*4 + (size_t)NE*4 + 4;
    cudaFuncSetAttribute(vq_kernel, cudaFuncAttributeMaxDynamicSharedMemorySize, (int)vq_smem);
    vq_kernel<<<MROWS/32, NE, vq_smem>>>(lat, cb0, cb1, cb2, xq,
                                         out + OFF_IDX, out + OFF_OH, out + OFF_LG, 32);
    finalize_kernel<<<1,1>>>(out + OFF_LOSS);

    // decoder
    gemm_nt_kernel<128,128,16,8,8,true ><<<dim3(1,         MROWS/128), 256>>>(xq, dw[0], db[0], g0, MROWS, 128,  32);
    gemm_nt_kernel<128,128,16,8,8,true ><<<dim3(256/128,   MROWS/128), 256>>>(g0, dw[1], db[1], g1, MROWS, 256, 128);
    gemm_nt_kernel<128,128,16,8,8,true ><<<dim3(512/128,   MROWS/128), 256>>>(g1, dw[2], db[2], g2, MROWS, 512, 256);
    gemm_nt_kernel<128,128,16,8,8,false><<<dim3(1024/128,  MROWS/128), 256>>>(g2, dw[3], db[3], out + OFF_OUT, MROWS, 1024, 512);
}

// round 3
// speedup vs baseline: 1.3372x; 1.3372x over previous
#include <cuda_runtime.h>
#include <cstdint>

#define MROWS 32768
#define NQ 3
#define NE 256
#define ED 32
#define CBPAD 33

// ---------------- scratch ----------------
__device__ float g_loss;
__device__ float g_h0[(size_t)MROWS * 512];
__device__ float g_h1[(size_t)MROWS * 256];
__device__ float g_h2[(size_t)MROWS * 128];
__device__ float g_lat[(size_t)MROWS * ED];
__device__ float g_xq [(size_t)MROWS * ED];
__device__ float g_g0[(size_t)MROWS * 128];
__device__ float g_g1[(size_t)MROWS * 256];
__device__ float g_g2[(size_t)MROWS * 512];

__device__ __forceinline__ uint32_t tf32_hi_bits(float x) {
    uint32_t u; asm("cvt.rna.tf32.f32 %0, %1;" : "=r"(u) : "f"(x)); return u;
}

__device__ __forceinline__ void mma_tf32(float* c, const uint32_t* a, const uint32_t* b) {
    asm volatile(
        "mma.sync.aligned.m16n8k8.row.col.f32.tf32.tf32.f32 "
        "{%0,%1,%2,%3}, {%4,%5,%6,%7}, {%8,%9}, {%0,%1,%2,%3};"
        : "+f"(c[0]), "+f"(c[1]), "+f"(c[2]), "+f"(c[3])
        : "r"(a[0]), "r"(a[1]), "r"(a[2]), "r"(a[3]), "r"(b[0]), "r"(b[1]));
}

// ---------------- HMMA 3xTF32 GEMM: C = relu?(A(MxK) @ W(NxK)^T + bias) ----------------
// CTA tile 128(M) x 64(N) x 32(K). 256 threads, 8 warps (4M x 2N), warp tile 32x32.
#define APITCH 36
// smem words: A_hi(128*36) A_lo(128*36) B_hi(64*36) B_lo(64*36)
#define SM_A_HI 0
#define SM_A_LO (128 * APITCH)
#define SM_B_HI (256 * APITCH)
#define SM_B_LO (320 * APITCH)
#define SM_WORDS (384 * APITCH)

template<bool RELU>
__global__ void __launch_bounds__(256, 2)
gemm_hmma_kernel(const float* __restrict__ A, const float* __restrict__ W,
                 const float* __restrict__ bias, float* __restrict__ C,
                 int N, int K)
{
    extern __shared__ uint32_t sm[];

    const int tid = threadIdx.x;
    const int bn = blockIdx.x * 64;
    const int bm = blockIdx.y * 128;
    const int w = tid >> 5, lane = tid & 31;
    const int wm = (w & 3) * 32;     // warp M offset in tile
    const int wn = (w >> 2) * 32;    // warp N offset in tile
    const int qr = lane >> 2;        // 0..7
    const int qc = lane & 3;         // 0..3

    float acc[2][4][4];
    #pragma unroll
    for (int i = 0; i < 2; i++)
        #pragma unroll
        for (int j = 0; j < 4; j++)
            #pragma unroll
            for (int k = 0; k < 4; k++) acc[i][j][k] = 0.f;

    const int nk = K >> 5;
    const int k4 = K >> 2;

    for (int ck = 0; ck < nk; ck++) {
        // ---- stage gmem -> split tf32 hi/lo -> smem ----
        const float4* Ag = (const float4*)A + (size_t)bm * k4 + ck * 8;
        const float4* Wg = (const float4*)W + (size_t)bn * k4 + ck * 8;
        if (ck > 0) __syncthreads();
        #pragma unroll
        for (int i = 0; i < 4; i++) {               // A: 1024 float4
            int idx = tid + i * 256;
            int r = idx >> 3, c4 = idx & 7;
            float4 v = Ag[(size_t)r * k4 + c4];
            uint32_t* hp = &sm[SM_A_HI + r * APITCH + c4 * 4];
            uint32_t* lp = &sm[SM_A_LO + r * APITCH + c4 * 4];
            uint32_t h;
            h = tf32_hi_bits(v.x); hp[0] = h; lp[0] = tf32_hi_bits(v.x - __uint_as_float(h));
            h = tf32_hi_bits(v.y); hp[1] = h; lp[1] = tf32_hi_bits(v.y - __uint_as_float(h));
            h = tf32_hi_bits(v.z); hp[2] = h; lp[2] = tf32_hi_bits(v.z - __uint_as_float(h));
            h = tf32_hi_bits(v.w); hp[3] = h; lp[3] = tf32_hi_bits(v.w - __uint_as_float(h));
        }
        #pragma unroll
        for (int i = 0; i < 2; i++) {               // B: 512 float4
            int idx = tid + i * 256;
            int r = idx >> 3, c4 = idx & 7;
            float4 v = Wg[(size_t)r * k4 + c4];
            uint32_t* hp = &sm[SM_B_HI + r * APITCH + c4 * 4];
            uint32_t* lp = &sm[SM_B_LO + r * APITCH + c4 * 4];
            uint32_t h;
            h = tf32_hi_bits(v.x); hp[0] = h; lp[0] = tf32_hi_bits(v.x - __uint_as_float(h));
            h = tf32_hi_bits(v.y); hp[1] = h; lp[1] = tf32_hi_bits(v.y - __uint_as_float(h));
            h = tf32_hi_bits(v.z); hp[2] = h; lp[2] = tf32_hi_bits(v.z - __uint_as_float(h));
            h = tf32_hi_bits(v.w); hp[3] = h; lp[3] = tf32_hi_bits(v.w - __uint_as_float(h));
        }
        __syncthreads();

        // ---- compute: 4 k-steps of 8 ----
        #pragma unroll
        for (int ks = 0; ks < 4; ks++) {
            const int k0 = ks * 8;
            uint32_t ahi[2][4], bhi[4][2], tmp[4][2];
            // A hi fragments (2 m-tiles of 16)
            #pragma unroll
            for (int mt = 0; mt < 2; mt++) {
                const uint32_t* base = &sm[SM_A_HI + (wm + mt * 16 + qr) * APITCH + k0 + qc];
                ahi[mt][0] = base[0];
                ahi[mt][1] = base[8 * APITCH];
                ahi[mt][2] = base[4];
                ahi[mt][3] = base[8 * APITCH + 4];
            }
            // B hi fragments (4 n-tiles of 8)  b0:(k=qc, n=qr[0..7]) b1:k=qc+4
            #pragma unroll
            for (int nt = 0; nt < 4; nt++) {
                const uint32_t* base = &sm[SM_B_HI + (wn + nt * 8 + qr) * APITCH + k0 + qc];
                bhi[nt][0] = base[0];
                bhi[nt][1] = base[4];
            }
            // pass 1: hi * hi
            #pragma unroll
            for (int mt = 0; mt < 2; mt++)
                #pragma unroll
                for (int nt = 0; nt < 4; nt++)
                    mma_tf32(acc[mt][nt], ahi[mt], bhi[nt]);
            // pass 2: hi * lo
            #pragma unroll
            for (int nt = 0; nt < 4; nt++) {
                const uint32_t* base = &sm[SM_B_LO + (wn + nt * 8 + qr) * APITCH + k0 + qc];
                tmp[nt][0] = base[0];
                tmp[nt][1] = base[4];
            }
            #pragma unroll
            for (int mt = 0; mt < 2; mt++)
                #pragma unroll
                for (int nt = 0; nt < 4; nt++)
                    mma_tf32(acc[mt][nt], ahi[mt], tmp[nt]);
            // pass 3: lo * hi
            uint32_t alo[2][4];
            #pragma unroll
            for (int mt = 0; mt < 2; mt++) {
                const uint32_t* base = &sm[SM_A_LO + (wm + mt * 16 + qr) * APITCH + k0 + qc];
                alo[mt][0] = base[0];
                alo[mt][1] = base[8 * APITCH];
                alo[mt][2] = base[4];
                alo[mt][3] = base[8 * APITCH + 4];
            }
            #pragma unroll
            for (int mt = 0; mt < 2; mt++)
                #pragma unroll
                for (int nt = 0; nt < 4; nt++)
                    mma_tf32(acc[mt][nt], alo[mt], bhi[nt]);
        }
    }

    // ---- epilogue: bias + relu, direct stores (float2, coalesced per quad) ----
    #pragma unroll
    for (int nt = 0; nt < 4; nt++) {
        const int col = bn + wn + nt * 8 + qc * 2;
        const float b0 = bias[col], b1 = bias[col + 1];
        #pragma unroll
        for (int mt = 0; mt < 2; mt++) {
            const int row = bm + wm + mt * 16 + qr;
            float2 v0, v1;
            v0.x = acc[mt][nt][0] + b0; v0.y = acc[mt][nt][1] + b1;
            v1.x = acc[mt][nt][2] + b0; v1.y = acc[mt][nt][3] + b1;
            if (RELU) {
                v0.x = fmaxf(v0.x, 0.f); v0.y = fmaxf(v0.y, 0.f);
                v1.x = fmaxf(v1.x, 0.f); v1.y = fmaxf(v1.y, 0.f);
            }
            *(float2*)(C + (size_t)row * N + col) = v0;
            *(float2*)(C + (size_t)(row + 8) * N + col) = v1;
        }
    }
}

// ---------------- SIMT fp32 GEMM (N=32 latent layer) ----------------
template<int BM, int BN, int BK, int TM, int TN, bool RELU>
__global__ void __launch_bounds__((BM/TM)*(BN/TN))
gemm_nt_kernel(const float* __restrict__ A, const float* __restrict__ W,
               const float* __restrict__ bias, float* __restrict__ C,
               int M, int N, int K)
{
    constexpr int THREADS = (BM/TM)*(BN/TN);
    __shared__ float As[BK][BM];
    __shared__ float Ws[BK][BN];

    const int bm = blockIdx.y * BM;
    const int bn = blockIdx.x * BN;
    const int tid = threadIdx.x;
    const int tn = (tid % (BN/TN)) * TN;
    const int tm = (tid / (BN/TN)) * TM;

    float acc[TM][TN];
    #pragma unroll
    for (int i = 0; i < TM; i++)
        #pragma unroll
        for (int j = 0; j < TN; j++) acc[i][j] = 0.f;

    for (int k0 = 0; k0 < K; k0 += BK) {
        constexpr int A_LOADS = (BM*BK) / (4*THREADS);
        #pragma unroll
        for (int i = 0; i < A_LOADS; i++) {
            int idx = (tid + i*THREADS) * 4;
            int r = idx / BK, c = idx % BK;
            float4 v = *(const float4*)(A + (size_t)(bm + r)*K + k0 + c);
            As[c+0][r] = v.x; As[c+1][r] = v.y; As[c+2][r] = v.z; As[c+3][r] = v.w;
        }
        constexpr int W_LOADS = (BN*BK) / (4*THREADS);
        #pragma unroll
        for (int i = 0; i < W_LOADS; i++) {
            int idx = (tid + i*THREADS) * 4;
            int r = idx / BK, c = idx % BK;
            float4 v = *(const float4*)(W + (size_t)(bn + r)*K + k0 + c);
            Ws[c+0][r] = v.x; Ws[c+1][r] = v.y; Ws[c+2][r] = v.z; Ws[c+3][r] = v.w;
        }
        __syncthreads();

        #pragma unroll
        for (int k = 0; k < BK; k++) {
            float ar[TM], wr[TN];
            #pragma unroll
            for (int i = 0; i < TM; i += 4) {
                float4 v = *(const float4*)(&As[k][tm + i]);
                ar[i+0] = v.x; ar[i+1] = v.y; ar[i+2] = v.z; ar[i+3] = v.w;
            }
            #pragma unroll
            for (int j = 0; j < TN; j += 4) {
                float4 v = *(const float4*)(&Ws[k][tn + j]);
                wr[j+0] = v.x; wr[j+1] = v.y; wr[j+2] = v.z; wr[j+3] = v.w;
            }
            #pragma unroll
            for (int i = 0; i < TM; i++)
                #pragma unroll
                for (int j = 0; j < TN; j++)
                    acc[i][j] = fmaf(ar[i], wr[j], acc[i][j]);
        }
        __syncthreads();
    }

    #pragma unroll
    for (int i = 0; i < TM; i++)
        #pragma unroll
        for (int j = 0; j < TN; j++) {
            float v = acc[i][j] + bias[bn + tn + j];
            if (RELU) v = fmaxf(v, 0.f);
            C[(size_t)(bm + tm + i)*N + bn + tn + j] = v;
        }
}

// ---------------- fused residual-VQ kernel ----------------
__global__ void __launch_bounds__(NE)
vq_kernel(const float* __restrict__ latent,
          const float* __restrict__ cb0, const float* __restrict__ cb1,
          const float* __restrict__ cb2,
          float* __restrict__ xq,
          float* __restrict__ out_idx, float* __restrict__ out_oh,
          float* __restrict__ out_logits,
          int rows_per_block)
{
    extern __shared__ float smf[];
    float* cbs   = smf;
    float* cnorm = cbs + NQ*NE*CBPAD;
    float* resid = cnorm + NQ*NE;
    float* xqrow = resid + ED;
    float* red_v = xqrow + ED;
    int*   red_i = (int*)(red_v + NE);
    float* s_rn  = (float*)(red_i + NE);

    const int t = threadIdx.x;

    const float* srcs[NQ] = {cb0, cb1, cb2};
    for (int q = 0; q < NQ; q++)
        for (int i = t; i < NE*ED; i += NE) {
            int r = i / ED, c = i % ED;
            cbs[(q*NE + r)*CBPAD + c] = srcs[q][i];
        }
    __syncthreads();
    for (int q = 0; q < NQ; q++) {
        const float* row = &cbs[(q*NE + t)*CBPAD];
        float s = 0.f;
        #pragma unroll
        for (int k = 0; k < ED; k++) s = fmaf(row[k], row[k], s);
        cnorm[q*NE + t] = s;
    }
    __syncthreads();

    float loss_acc = 0.f;
    const int row0 = blockIdx.x * rows_per_block;
    const int row1 = min(row0 + rows_per_block, MROWS);

    for (int r = row0; r < row1; r++) {
        if (t < ED) { resid[t] = latent[(size_t)r*ED + t]; xqrow[t] = 0.f; }
        __syncthreads();

        for (int q = 0; q < NQ; q++) {
            if (t < 32) {
                float v = resid[t]; v = v*v;
                #pragma unroll
                for (int o = 16; o; o >>= 1) v += __shfl_xor_sync(0xffffffffu, v, o);
                if (t == 0) s_rn[0] = v;
            }
            __syncthreads();
            const float rnorm = s_rn[0];

            const float* crow = &cbs[(q*NE + t)*CBPAD];
            float dot = 0.f;
            #pragma unroll
            for (int k = 0; k < ED; k++) dot = fmaf(resid[k], crow[k], dot);
            float d = rnorm + cnorm[q*NE + t] - 2.f*dot;
            out_logits[((size_t)r*NQ + q)*NE + t] = d;

            red_v[t] = d; red_i[t] = t;
            __syncthreads();
            #pragma unroll
            for (int s = NE/2; s > 0; s >>= 1) {
                if (t < s) {
                    float v2 = red_v[t+s]; int i2 = red_i[t+s];
                    if (v2 < red_v[t] || (v2 == red_v[t] && i2 < red_i[t])) {
                        red_v[t] = v2; red_i[t] = i2;
                    }
                }
                __syncthreads();
            }
            const int best = red_i[0];

            out_oh[((size_t)r*NQ + q)*NE + t] = (t == best) ? 1.f : 0.f;
            if (t == 0) out_idx[(size_t)r*NQ + q] = (float)best;

            if (t < 32) {
                float c  = cbs[(q*NE + best)*CBPAD + t];
                float rv = resid[t];
                float diff = c - rv;
                float xres = rv + diff;
                float sq = diff*diff;
                #pragma unroll
                for (int o = 16; o; o >>= 1) sq += __shfl_xor_sync(0xffffffffu, sq, o);
                if (t == 0) loss_acc += sq;
                resid[t] = rv - xres;
                xqrow[t] += xres;
            }
            __syncthreads();
        }
        if (t < ED) xq[(size_t)r*ED + t] = xqrow[t];
        __syncthreads();
    }
    if (t == 0) atomicAdd(&g_loss, loss_acc);
}

__global__ void zero_loss_kernel() { g_loss = 0.f; }

__global__ void finalize_kernel(float* __restrict__ loss_out)
{
    loss_out[0] = g_loss * (1.25f / (3.0f * (float)MROWS * (float)ED));
}

// ---------------- launch ----------------
extern "C" void kernel_launch(void* const* d_in, const int* in_sizes, int n_in,
                              void* d_out, int out_size)
{
    const float* x   = (const float*)d_in[0];
    const float* ew[4] = {(const float*)d_in[1], (const float*)d_in[3],
                          (const float*)d_in[5], (const float*)d_in[7]};
    const float* eb[4] = {(const float*)d_in[2], (const float*)d_in[4],
                          (const float*)d_in[6], (const float*)d_in[8]};
    const float* dw[4] = {(const float*)d_in[9],  (const float*)d_in[11],
                          (const float*)d_in[13], (const float*)d_in[15]};
    const float* db[4] = {(const float*)d_in[10], (const float*)d_in[12],
                          (const float*)d_in[14], (const float*)d_in[16]};
    const float* cb0 = (const float*)d_in[17];
    const float* cb1 = (const float*)d_in[18];
    const float* cb2 = (const float*)d_in[19];
    float* out = (float*)d_out;

    float *h0, *h1, *h2, *lat, *xq, *g0, *g1, *g2;
    cudaGetSymbolAddress((void**)&h0,  g_h0);
    cudaGetSymbolAddress((void**)&h1,  g_h1);
    cudaGetSymbolAddress((void**)&h2,  g_h2);
    cudaGetSymbolAddress((void**)&lat, g_lat);
    cudaGetSymbolAddress((void**)&xq,  g_xq);
    cudaGetSymbolAddress((void**)&g0,  g_g0);
    cudaGetSymbolAddress((void**)&g1,  g_g1);
    cudaGetSymbolAddress((void**)&g2,  g_g2);

    const size_t OFF_OUT  = 0;
    const size_t OFF_LOSS = (size_t)MROWS * 1024;
    const size_t OFF_IDX  = OFF_LOSS + 1;
    const size_t OFF_OH   = OFF_IDX + (size_t)MROWS * NQ;
    const size_t OFF_LG   = OFF_OH  + (size_t)MROWS * NQ * NE;

    const int SMEM_BYTES = SM_WORDS * 4;
    cudaFuncSetAttribute(gemm_hmma_kernel<true>,  cudaFuncAttributeMaxDynamicSharedMemorySize, SMEM_BYTES);
    cudaFuncSetAttribute(gemm_hmma_kernel<false>, cudaFuncAttributeMaxDynamicSharedMemorySize, SMEM_BYTES);

    const int MT = MROWS / 128;

    // encoder
    gemm_hmma_kernel<true ><<<dim3(8, MT), 256, SMEM_BYTES>>>(x,  ew[0], eb[0], h0,  512, 1024);
    gemm_hmma_kernel<true ><<<dim3(4, MT), 256, SMEM_BYTES>>>(h0, ew[1], eb[1], h1,  256, 512);
    gemm_hmma_kernel<true ><<<dim3(2, MT), 256, SMEM_BYTES>>>(h1, ew[2], eb[2], h2,  128, 256);
    gemm_nt_kernel<128, 32,16,8,4,false><<<dim3(1, MT), 128>>>(h2, ew[3], eb[3], lat, MROWS, 32, 128);

    // residual VQ
    zero_loss_kernel<<<1,1>>>();
    const size_t vq_smem = (size_t)(NQ*NE*CBPAD + NQ*NE + 2*ED + NE)*4 + (size_t)NE*4 + 4;
    cudaFuncSetAttribute(vq_kernel, cudaFuncAttributeMaxDynamicSharedMemorySize, (int)vq_smem);
    vq_kernel<<<MROWS/32, NE, vq_smem>>>(lat, cb0, cb1, cb2, xq,
                                         out + OFF_IDX, out + OFF_OH, out + OFF_LG, 32);
    finalize_kernel<<<1,1>>>(out + OFF_LOSS);

    // decoder
    gemm_hmma_kernel<true ><<<dim3(2,  MT), 256, SMEM_BYTES>>>(xq, dw[0], db[0], g0, 128,  32);
    gemm_hmma_kernel<true ><<<dim3(4,  MT), 256, SMEM_BYTES>>>(g0, dw[1], db[1], g1, 256, 128);
    gemm_hmma_kernel<true ><<<dim3(8,  MT), 256, SMEM_BYTES>>>(g1, dw[2], db[2], g2, 512, 256);
    gemm_hmma_kernel<false><<<dim3(16, MT), 256, SMEM_BYTES>>>(g2, dw[3], db[3], out + OFF_OUT, 1024, 512);
}